// round 2
// baseline (speedup 1.0000x reference)
#include <cuda_runtime.h>
#include <cstdint>

// out[src] += feat[dst] * w  ; feat: [N,64] f32, E=1e6
//
// Inputs (metadata order):
//   d_in[0] = feat        float32 [N*64]
//   d_in[1] = edge_weight float32 [E]
//   d_in[2] = edge_src    int32   [E]   (JAX x64 disabled -> int64 request becomes int32)
//   d_in[3] = edge_dst    int32   [E]
// Output: float32 [N*64]

__global__ void zero_kernel(float4* __restrict__ out, int n4) {
    int i = blockIdx.x * blockDim.x + threadIdx.x;
    if (i < n4) out[i] = make_float4(0.f, 0.f, 0.f, 0.f);
}

__global__ __launch_bounds__(256) void gcn_scatter_kernel(
    const float* __restrict__ feat,
    const float* __restrict__ ew,
    const int*   __restrict__ esrc,
    const int*   __restrict__ edst,
    float* __restrict__ out,
    int n_edges)
{
    int gid  = blockIdx.x * blockDim.x + threadIdx.x;
    int e    = gid >> 4;        // 16 threads per edge
    int lane = gid & 15;        // each handles one float4 (16B) of the 256B row
    if (e >= n_edges) return;

    int   s = __ldg(&esrc[e]);
    int   d = __ldg(&edst[e]);
    float w = __ldg(&ew[e]);

    const float4* frow = reinterpret_cast<const float4*>(feat + (long long)d * 64);
    float4 v = __ldg(&frow[lane]);
    v.x *= w; v.y *= w; v.z *= w; v.w *= w;

    float* dst = out + (long long)s * 64 + lane * 4;
    // Vector reduction (no return) — 1 L2 RMW op per 16B instead of 4 scalar atomics.
    asm volatile("red.global.add.v4.f32 [%0], {%1, %2, %3, %4};"
                 :: "l"(dst), "f"(v.x), "f"(v.y), "f"(v.z), "f"(v.w)
                 : "memory");
}

extern "C" void kernel_launch(void* const* d_in, const int* in_sizes, int n_in,
                              void* d_out, int out_size)
{
    const float* feat = (const float*)d_in[0];
    const float* ew   = (const float*)d_in[1];
    const int*   esrc = (const int*)d_in[2];
    const int*   edst = (const int*)d_in[3];
    float*       out  = (float*)d_out;

    int n_edges = in_sizes[1];          // E (from edge_weight)
    int n4      = out_size / 4;         // float4 count of output

    zero_kernel<<<(n4 + 255) / 256, 256>>>((float4*)out, n4);

    long long total = (long long)n_edges * 16;
    int blocks = (int)((total + 255) / 256);
    gcn_scatter_kernel<<<blocks, 256>>>(feat, ew, esrc, edst, out, n_edges);
}